// round 13
// baseline (speedup 1.0000x reference)
#include <cuda_runtime.h>
#include <cuda_bf16.h>
#include <math.h>

#define B 64
#define C 512
#define HW 1024
#define R 32
#define T1 128
#define TN 64          // n per pass1 tile
#define NTILE 16       // HW / TN
#define NSLOT 16       // one pooled partial per tile
#define CK 32          // channels per chunk
#define NCHUNK 16      // C / CK

// cp.async helpers (Ampere+)
#define CP_ASYNC16(dst_u32, src_ptr) \
    asm volatile("cp.async.cg.shared.global [%0], [%1], 16;" \
                 :: "r"(dst_u32), "l"(src_ptr))
#define CP_COMMIT() asm volatile("cp.async.commit_group;" ::: "memory")
#define CP_WAIT1()  asm volatile("cp.async.wait_group 1;" ::: "memory")

// m16n8k16 row.col bf16 mma, fp32 accumulate
#define MMA_BF16(D, A0, A1, A2, A3, B0, B1)                                    \
    asm volatile(                                                              \
        "mma.sync.aligned.m16n8k16.row.col.f32.bf16.bf16.f32 "                 \
        "{%0,%1,%2,%3}, {%4,%5,%6,%7}, {%8,%9}, {%0,%1,%2,%3};"                \
        : "+f"(D[0]), "+f"(D[1]), "+f"(D[2]), "+f"(D[3])                       \
        : "r"(A0), "r"(A1), "r"(A2), "r"(A3), "r"(B0), "r"(B1))

// ---------------- scratch (device globals: no allocation allowed) -------------
__device__ float g_featT[B * HW * R];       // 8 MB  featT[b][n][r] (no bias)
__device__ __align__(256) __nv_bfloat16 g_whi[R * C];   // 32 KB weight hi
__device__ __align__(256) __nv_bfloat16 g_wlo[R * C];   // 32 KB weight lo
__device__ float g_poolpart[B * NSLOT * C]; // 2 MB   partial sums for pooled
__device__ float g_covpart[B * 4 * R * R];  // 1 MB   raw Gram partials
__device__ float g_sp[B * HW];              // 256 KB spatial logits (no bias)
__device__ float g_ca[B * C];               // 128 KB channel attention
__device__ float g_att[B * HW];             // 256 KB eigen_att * spatial_att

// ============================================================================
// Pass 0: split w_eig into bf16 hi/lo (bf16x3 decomposition), layout [r][c].
// ============================================================================
__global__ __launch_bounds__(256) void pass0(const float* __restrict__ w_eig) {
    int i = blockIdx.x * 256 + threadIdx.x;   // grid 64 -> 16384
    float v = w_eig[i];
    __nv_bfloat16 h = __float2bfloat16(v);
    g_whi[i] = h;
    g_wlo[i] = __float2bfloat16(v - __bfloat162float(h));
}

// ============================================================================
// Pass 1: bf16x3 tensor-core GEMM producing featT[b][n][r], plus pooled and
// spatial side-products. CTA = (b, 64-n tile), grid 1024, 128 thr / 4 warps.
// Per chunk (32 ch): cp.async raw x tile [32c][64n] fp32 + bf16 weight slices;
// convert/transpose raw -> xsh/xsl[n][c]; 2 k16-steps x 4 r-tiles x 3 splits
// of m16n8k16 mma. RACE FIX vs R11: next-chunk copies are issued AFTER the
// mma loop, so the in-flight writes never target the weight buffer the mma
// is reading (cc and cc+2 share parity).
// ============================================================================
__global__ __launch_bounds__(T1) void pass1(const float* __restrict__ x,
                                            const float* __restrict__ w_sp) {
    __shared__ __align__(16) float raw[2][CK][TN];            // 16 KB
    __shared__ __align__(16) unsigned short xsh[TN][42];      // 5.25 KB
    __shared__ __align__(16) unsigned short xsl[TN][42];      // 5.25 KB
    __shared__ __align__(16) unsigned short wsh[2][R][40];    // 5 KB
    __shared__ __align__(16) unsigned short wsl[2][R][40];    // 5 KB
    __shared__ float wsp_s[C];                                // 2 KB
    __shared__ float spool[C];                                // 2 KB
    __shared__ float sps[2][TN];                              // 0.5 KB

    int bx = blockIdx.x;
    int b = bx >> 4;
    int tile = bx & 15;
    int n0 = tile * TN;
    int tid = threadIdx.x, lane = tid & 31, warp = tid >> 5;
    int g = lane >> 2, tg2 = (lane & 3) * 2;
    int nb = warp * 16;              // warp's 16-n slice

    const float* xg = x + ((size_t)b * C) * HW + n0;
    unsigned int raw_base = (unsigned int)__cvta_generic_to_shared(&raw[0][0][0]);
    unsigned int wsh_base = (unsigned int)__cvta_generic_to_shared(&wsh[0][0][0]);
    unsigned int wsl_base = (unsigned int)__cvta_generic_to_shared(&wsl[0][0][0]);

    // issue copies for chunk CC: raw x tile (4 segs/thread) + w slices (2)
#define ISSUE_CHUNK(CC)                                                        \
    {                                                                          \
        int bf_ = (CC) & 1;                                                    \
        _Pragma("unroll")                                                      \
        for (int j_ = 0; j_ < 4; j_++) {                                       \
            int s_ = tid + j_ * T1;                                            \
            int ch_ = s_ >> 4;               /* 0..31 */                       \
            int nf_ = (s_ & 15) << 2;        /* float offset */                \
            const float* src_ = xg + (size_t)((CC) * CK + ch_) * HW + nf_;     \
            unsigned int dst_ = raw_base + ((bf_ * CK + ch_) * TN + nf_) * 4u; \
            CP_ASYNC16(dst_, src_);                                            \
        }                                                                      \
        {                                                                      \
            int r_ = tid >> 2, k_ = tid & 3; /* 32 rows x 4 segs */            \
            const char* sh_ = (const char*)g_whi + (r_ * C + (CC) * CK) * 2 + k_ * 16; \
            const char* sl_ = (const char*)g_wlo + (r_ * C + (CC) * CK) * 2 + k_ * 16; \
            unsigned int dh_ = wsh_base + (bf_ * R * 40 + r_ * 40) * 2u + k_ * 16u;   \
            unsigned int dl_ = wsl_base + (bf_ * R * 40 + r_ * 40) * 2u + k_ * 16u;   \
            CP_ASYNC16(dh_, sh_);                                              \
            CP_ASYNC16(dl_, sl_);                                              \
        }                                                                      \
    }

    ISSUE_CHUNK(0) CP_COMMIT();
    ISSUE_CHUNK(1) CP_COMMIT();

    for (int idx = tid; idx < C; idx += T1) wsp_s[idx] = w_sp[idx];

    float acc[4][4];                 // [r-tile rbi][d0..d3]
#pragma unroll
    for (int i = 0; i < 4; i++)
#pragma unroll
        for (int j = 0; j < 4; j++) acc[i][j] = 0.f;
    float sp = 0.f;
    int sp_n = tid & 63, sp_ch = tid >> 6;   // spatial duty: 2 threads per n

    for (int cc = 0; cc < NCHUNK; cc++) {
        int buf = cc & 1;
        CP_WAIT1();
        __syncthreads();   // raw/ws for cc visible; xs of cc-1 fully consumed

        // duty 1: pooled partial per channel (warp-owned, shfl chain)
#pragma unroll
        for (int j = 0; j < 8; j++) {
            int k = warp + j * 4;
            float t = raw[buf][k][lane] + raw[buf][k][lane + 32];
            t += __shfl_xor_sync(0xffffffffu, t, 16);
            t += __shfl_xor_sync(0xffffffffu, t, 8);
            t += __shfl_xor_sync(0xffffffffu, t, 4);
            t += __shfl_xor_sync(0xffffffffu, t, 2);
            t += __shfl_xor_sync(0xffffffffu, t, 1);
            if (lane == 0) spool[cc * CK + k] = t;
        }
        // duty 2: spatial logits (thread owns n, half the channels)
#pragma unroll
        for (int j = 0; j < 16; j++) {
            int k = sp_ch * 16 + j;
            sp = fmaf(wsp_s[cc * CK + k], raw[buf][k][sp_n], sp);
        }
        // convert + transpose: raw[c][n] fp32 -> xsh/xsl[n][c] bf16 pairs
        {
            int n = tid & 63;
            int cp0 = (tid >> 6) * 2;    // 0 or 2
#pragma unroll
            for (int j = 0; j < 8; j++) {
                int c = cp0 + j * 4;
                float v0 = raw[buf][c][n];
                float v1 = raw[buf][c + 1][n];
                __nv_bfloat16 h0 = __float2bfloat16(v0);
                __nv_bfloat16 h1 = __float2bfloat16(v1);
                __nv_bfloat16 l0 = __float2bfloat16(v0 - __bfloat162float(h0));
                __nv_bfloat16 l1 = __float2bfloat16(v1 - __bfloat162float(h1));
                *(unsigned int*)&xsh[n][c] =
                    ((unsigned int)__bfloat16_as_ushort(h1) << 16) |
                    __bfloat16_as_ushort(h0);
                *(unsigned int*)&xsl[n][c] =
                    ((unsigned int)__bfloat16_as_ushort(l1) << 16) |
                    __bfloat16_as_ushort(l0);
            }
        }
        __syncthreads();   // xs ready; all raw[buf]/old-ws reads complete

        // mma: 2 k16-steps; A = xT (n x c) row-major, B = w^T col-major
#pragma unroll
        for (int ks = 0; ks < 2; ks++) {
            int cb = ks * 16;
            unsigned int ah0 = *(const unsigned int*)&xsh[nb + g][cb + tg2];
            unsigned int ah1 = *(const unsigned int*)&xsh[nb + g + 8][cb + tg2];
            unsigned int ah2 = *(const unsigned int*)&xsh[nb + g][cb + 8 + tg2];
            unsigned int ah3 = *(const unsigned int*)&xsh[nb + g + 8][cb + 8 + tg2];
            unsigned int al0 = *(const unsigned int*)&xsl[nb + g][cb + tg2];
            unsigned int al1 = *(const unsigned int*)&xsl[nb + g + 8][cb + tg2];
            unsigned int al2 = *(const unsigned int*)&xsl[nb + g][cb + 8 + tg2];
            unsigned int al3 = *(const unsigned int*)&xsl[nb + g + 8][cb + 8 + tg2];
#pragma unroll
            for (int rbi = 0; rbi < 4; rbi++) {
                int rr = rbi * 8 + g;
                unsigned int bh0 = *(const unsigned int*)&wsh[buf][rr][cb + tg2];
                unsigned int bh1 = *(const unsigned int*)&wsh[buf][rr][cb + 8 + tg2];
                unsigned int bl0 = *(const unsigned int*)&wsl[buf][rr][cb + tg2];
                unsigned int bl1 = *(const unsigned int*)&wsl[buf][rr][cb + 8 + tg2];
                MMA_BF16(acc[rbi], ah0, ah1, ah2, ah3, bh0, bh1);
                MMA_BF16(acc[rbi], al0, al1, al2, al3, bh0, bh1);
                MMA_BF16(acc[rbi], ah0, ah1, ah2, ah3, bl0, bl1);
            }
        }

        // RACE FIX: issue chunk+2 only after this chunk's mma reads are done.
        // raw[buf] reads ended before the 2nd barrier; wsh/wsl[buf] reads end
        // with each thread's mma above (program order per thread).
        if (cc + 2 < NCHUNK) ISSUE_CHUNK(cc + 2)
        CP_COMMIT();       // (possibly empty) keeps group counting aligned
    }
#undef ISSUE_CHUNK

    // epilogue: D[n][r] fragments -> g_featT (float2 per d-pair)
    {
        size_t nbase = (size_t)b * HW + n0 + nb;
#pragma unroll
        for (int rbi = 0; rbi < 4; rbi++) {
            *(float2*)&g_featT[(nbase + g) * R + rbi * 8 + tg2] =
                make_float2(acc[rbi][0], acc[rbi][1]);
            *(float2*)&g_featT[(nbase + g + 8) * R + rbi * 8 + tg2] =
                make_float2(acc[rbi][2], acc[rbi][3]);
        }
    }

    // combine the two spatial halves; store side products
    sps[sp_ch][sp_n] = sp;
    __syncthreads();
    if (tid < TN)
        g_sp[(size_t)b * HW + n0 + tid] = sps[0][tid] + sps[1][tid];
    for (int idx = tid; idx < C; idx += T1)
        g_poolpart[((size_t)(b * NSLOT) + tile) * C + idx] = spool[idx];
}

// ============================================================================
// Pass 2a: raw Gram partials from featT. CTA = (b, n-quarter), 256 threads.
// ============================================================================
__global__ __launch_bounds__(256) void pass2a() {
    __shared__ __align__(16) float fcT[256][36];
    int b = blockIdx.x >> 2;
    int q = blockIdx.x & 3;
    int tid = threadIdx.x;

    const float* src = g_featT + ((size_t)b * HW + q * 256) * R;
    for (int it = 0; it < 32; it++) {            // 8192 elems, coalesced
        int idx = tid + it * 256;
        fcT[idx >> 5][idx & 31] = src[idx];
    }
    __syncthreads();

    int my_r = tid >> 3;
    int s0 = (tid & 7) << 2;
    float g4[4] = {0.f, 0.f, 0.f, 0.f};
#pragma unroll 8
    for (int n = 0; n < 256; n++) {
        float fr = fcT[n][my_r];
        float4 fs = *(const float4*)&fcT[n][s0];
        g4[0] = fmaf(fr, fs.x, g4[0]);
        g4[1] = fmaf(fr, fs.y, g4[1]);
        g4[2] = fmaf(fr, fs.z, g4[2]);
        g4[3] = fmaf(fr, fs.w, g4[3]);
    }
    *(float4*)&g_covpart[((size_t)(b * 4 + q)) * (R * R) + my_r * R + s0] =
        make_float4(g4[0], g4[1], g4[2], g4[3]);
}

// ============================================================================
// Pass 2b: per-batch finish. pooled -> MLP (g_ca) + mu; cov assembly;
// power iteration; att projection + min/max + sigmoids.
// ============================================================================
__global__ __launch_bounds__(256) void pass2b(const float* __restrict__ w_fc1,
                                              const float* __restrict__ b_fc1,
                                              const float* __restrict__ w_fc2,
                                              const float* __restrict__ b_fc2,
                                              const float* __restrict__ w_eig,
                                              const float* __restrict__ b_sp,
                                              const float* __restrict__ v0) {
    __shared__ float s_pool[C];
    __shared__ float s_mu[R];
    __shared__ float s_ca1[R];
    __shared__ float s_cov[R * R];
    __shared__ float s_v[R];
    __shared__ float s_redmin[8], s_redmax[8];
    __shared__ float s_c0, s_amin, s_amax;

    int b = blockIdx.x;
    int tid = threadIdx.x, lane = tid & 31, warp = tid >> 5;

    // 1. pooled = sum of 16 tile partials / HW
    for (int c = tid; c < C; c += 256) {
        float s = 0.f;
#pragma unroll
        for (int k = 0; k < NSLOT; k++) s += g_poolpart[((size_t)b * NSLOT + k) * C + c];
        s_pool[c] = s * (1.0f / HW);
    }
    __syncthreads();

    // 2. ca1 = relu(pooled @ w_fc1^T + b_fc1); mu = w_eig @ pooled (fp32)
    for (int k = 0; k < 4; k++) {
        int r = warp + k * 8;
        float s1 = 0.f, s2 = 0.f;
        for (int c = lane; c < C; c += 32) {
            float p = s_pool[c];
            s1 = fmaf(p, w_fc1[r * C + c], s1);
            s2 = fmaf(p, w_eig[r * C + c], s2);
        }
        for (int o = 16; o > 0; o >>= 1) {
            s1 += __shfl_xor_sync(0xffffffffu, s1, o);
            s2 += __shfl_xor_sync(0xffffffffu, s2, o);
        }
        if (lane == 0) {
            s_ca1[r] = fmaxf(s1 + b_fc1[r], 0.f);
            s_mu[r] = s2;
        }
    }
    __syncthreads();

    // 3. channel attention: sigmoid(ca1 @ w_fc2^T + b_fc2)
    for (int c = tid; c < C; c += 256) {
        float a = b_fc2[c];
#pragma unroll
        for (int r = 0; r < R; r++) a = fmaf(s_ca1[r], w_fc2[c * R + r], a);
        g_ca[(size_t)b * C + c] = 1.f / (1.f + expf(-a));
    }

    // 4. cov = (sum_q G_q - HW*mu*mu^T)/(HW-1) + 1e-5 I
    for (int e0 = tid * 4; e0 < R * R; e0 += 256 * 4) {
#pragma unroll
        for (int i = 0; i < 4; i++) {
            int e = e0 + i;
            int r = e >> 5, s = e & 31;
            float gg = 0.f;
#pragma unroll
            for (int q = 0; q < 4; q++)
                gg += g_covpart[((size_t)(b * 4 + q)) * (R * R) + e];
            float v = (gg - (float)HW * s_mu[r] * s_mu[s]) * (1.0f / (HW - 1));
            if (r == s) v += 1e-5f;
            s_cov[e] = v;
        }
    }
    __syncthreads();

    // 5. power iteration (warp 0)
    if (warp == 0) {
        float v = v0[b * R + lane];
        float nr = v * v;
        for (int o = 16; o > 0; o >>= 1) nr += __shfl_xor_sync(0xffffffffu, nr, o);
        v = v / sqrtf(nr);
        for (int it = 0; it < 5; it++) {
            float nv = 0.f;
#pragma unroll
            for (int s = 0; s < R; s++)
                nv = fmaf(s_cov[s * R + lane], __shfl_sync(0xffffffffu, v, s), nv);
            float nn = nv * nv;
            for (int o = 16; o > 0; o >>= 1) nn += __shfl_xor_sync(0xffffffffu, nn, o);
            v = nv / (sqrtf(nn) + 1e-10f);
        }
        s_v[lane] = v;
        float c0 = v * s_mu[lane];
        for (int o = 16; o > 0; o >>= 1) c0 += __shfl_xor_sync(0xffffffffu, c0, o);
        if (lane == 0) s_c0 = c0;
    }
    __syncthreads();

    // 6. att[n] = v . featT[n][:] - c0 ; min/max; sigmoids
    float attv[4];
#pragma unroll
    for (int k = 0; k < 4; k++) {
        int n = k * 256 + tid;
        const float4* fp = (const float4*)&g_featT[((size_t)b * HW + n) * R];
        float a = 0.f;
#pragma unroll
        for (int q = 0; q < 8; q++) {
            float4 f = fp[q];
            a = fmaf(s_v[q * 4 + 0], f.x, a);
            a = fmaf(s_v[q * 4 + 1], f.y, a);
            a = fmaf(s_v[q * 4 + 2], f.z, a);
            a = fmaf(s_v[q * 4 + 3], f.w, a);
        }
        attv[k] = a - s_c0;
    }
    float mn = attv[0], mx = attv[0];
#pragma unroll
    for (int k = 1; k < 4; k++) { mn = fminf(mn, attv[k]); mx = fmaxf(mx, attv[k]); }
    for (int o = 16; o > 0; o >>= 1) {
        mn = fminf(mn, __shfl_xor_sync(0xffffffffu, mn, o));
        mx = fmaxf(mx, __shfl_xor_sync(0xffffffffu, mx, o));
    }
    if (lane == 0) { s_redmin[warp] = mn; s_redmax[warp] = mx; }
    __syncthreads();
    if (tid == 0) {
        float a = s_redmin[0], m = s_redmax[0];
        for (int w = 1; w < 8; w++) { a = fminf(a, s_redmin[w]); m = fmaxf(m, s_redmax[w]); }
        s_amin = a; s_amax = m;
    }
    __syncthreads();
    float amin = s_amin;
    float denom = (s_amax - amin) + 1e-10f;
    float bspv = b_sp[0];
#pragma unroll
    for (int k = 0; k < 4; k++) {
        int n = k * 256 + tid;
        float e = 1.f / (1.f + expf(-((attv[k] - amin) / denom)));
        float sl = g_sp[(size_t)b * HW + n] + bspv;
        float sa = 1.f / (1.f + expf(-sl));
        g_att[(size_t)b * HW + n] = e * sa;
    }
}

// ============================================================================
// Pass 3: out = x * (1 + ca[b,c] * att[b,n])  (2x float4 per thread; R8 form)
// ============================================================================
__global__ __launch_bounds__(256) void pass3(const float* __restrict__ x,
                                             float* __restrict__ out) {
    unsigned int base = blockIdx.x * 512u + threadIdx.x;
#pragma unroll
    for (int u = 0; u < 2; u++) {
        unsigned int i = base + u * 256u;      // float4 index
        int n4 = i & 255;                      // HW/4 = 256
        int c = (i >> 8) & (C - 1);
        int b = i >> 17;
        float ca = g_ca[b * C + c];
        float4 at = ((const float4*)g_att)[(size_t)b * (HW / 4) + n4];
        float4 xv = ((const float4*)x)[i];
        float4 o;
        o.x = fmaf(xv.x, ca * at.x, xv.x);
        o.y = fmaf(xv.y, ca * at.y, xv.y);
        o.z = fmaf(xv.z, ca * at.z, xv.z);
        o.w = fmaf(xv.w, ca * at.w, xv.w);
        ((float4*)out)[i] = o;
    }
}

extern "C" void kernel_launch(void* const* d_in, const int* in_sizes, int n_in,
                              void* d_out, int out_size) {
    const float* x     = (const float*)d_in[0];
    const float* w_fc1 = (const float*)d_in[1];
    const float* b_fc1 = (const float*)d_in[2];
    const float* w_fc2 = (const float*)d_in[3];
    const float* b_fc2 = (const float*)d_in[4];
    const float* w_eig = (const float*)d_in[5];
    /* d_in[6] = b_eig: cancels in feat_c and in mu -> unused */
    const float* w_sp  = (const float*)d_in[7];
    const float* b_sp  = (const float*)d_in[8];
    const float* v0    = (const float*)d_in[9];
    float* out = (float*)d_out;

    pass0<<<R * C / 256, 256>>>(w_eig);
    pass1<<<B * NTILE, T1>>>(x, w_sp);
    pass2a<<<B * 4, 256>>>();
    pass2b<<<B, 256>>>(w_fc1, b_fc1, w_fc2, b_fc2, w_eig, b_sp, v0);
    pass3<<<(B * C * HW / 4) / 512, 256>>>(x, out);
}

// round 14
// speedup vs baseline: 1.0940x; 1.0940x over previous
#include <cuda_runtime.h>
#include <cuda_bf16.h>
#include <math.h>

#define B 64
#define C 512
#define HW 1024
#define R 32
#define T1 128
#define TN 64          // n per pass1 tile
#define NTILE 16       // HW / TN
#define NSLOT 16       // one pooled partial per tile
#define CK 16          // channels per chunk
#define NCHUNK 32      // C / CK

// cp.async helpers (Ampere+)
#define CP_ASYNC16(dst_u32, src_ptr) \
    asm volatile("cp.async.cg.shared.global [%0], [%1], 16;" \
                 :: "r"(dst_u32), "l"(src_ptr))
#define CP_COMMIT() asm volatile("cp.async.commit_group;" ::: "memory")
#define CP_WAIT1()  asm volatile("cp.async.wait_group 1;" ::: "memory")

// m16n8k16 row.col bf16 mma, fp32 accumulate
#define MMA_BF16(D, A0, A1, A2, A3, B0, B1)                                    \
    asm volatile(                                                              \
        "mma.sync.aligned.m16n8k16.row.col.f32.bf16.bf16.f32 "                 \
        "{%0,%1,%2,%3}, {%4,%5,%6,%7}, {%8,%9}, {%0,%1,%2,%3};"                \
        : "+f"(D[0]), "+f"(D[1]), "+f"(D[2]), "+f"(D[3])                       \
        : "r"(A0), "r"(A1), "r"(A2), "r"(A3), "r"(B0), "r"(B1))

// ---------------- scratch (device globals: no allocation allowed) -------------
__device__ float g_featT[B * HW * R];       // 8 MB  featT[b][n][r] (no bias)
__device__ __align__(256) __nv_bfloat16 g_whi[R * C];   // 32 KB weight hi
__device__ __align__(256) __nv_bfloat16 g_wlo[R * C];   // 32 KB weight lo
__device__ float g_poolpart[B * NSLOT * C]; // 2 MB   partial sums for pooled
__device__ float g_covpart[B * 4 * R * R];  // 1 MB   raw Gram partials
__device__ float g_sp[B * HW];              // 256 KB spatial logits (no bias)
__device__ float g_ca[B * C];               // 128 KB channel attention
__device__ float g_att[B * HW];             // 256 KB final attention product
__device__ float g_attraw[B * HW];          // 256 KB raw attv values
__device__ float g_v[B * R];                // eigenvector per batch
__device__ float g_c0[B];                   // v . mu per batch
__device__ float g_mn[B * 8], g_mx[B * 8];  // per-tile min/max partials

// ============================================================================
// Pass 0: split w_eig into bf16 hi/lo (bf16x3 decomposition), layout [r][c].
// ============================================================================
__global__ __launch_bounds__(256) void pass0(const float* __restrict__ w_eig) {
    int i = blockIdx.x * 256 + threadIdx.x;   // grid 64 -> 16384
    float v = w_eig[i];
    __nv_bfloat16 h = __float2bfloat16(v);
    g_whi[i] = h;
    g_wlo[i] = __float2bfloat16(v - __bfloat162float(h));
}

// ============================================================================
// Pass 1: bf16x3 tensor-core GEMM -> featT[b][n][r]. CTA = (b, 64-n tile),
// grid 1024, 128 thr / 4 warps, ~31 KB smem -> multiple CTAs/SM (vs 1 in R13).
// 16-channel chunks, THREE-stage cp.async buffers: stage(cc+2) differs from
// stages read in cc and cc+1, so prefetch right after barrier1 is race-free.
// Per chunk: duty (pooled shfl chains warp c&3, spatial 2thr/n) + convert
// raw->xsh/xsl + 1 k16-step x 4 r-tiles x 3 splits of m16n8k16.
// ============================================================================
__global__ __launch_bounds__(T1) void pass1(const float* __restrict__ x,
                                            const float* __restrict__ w_sp) {
    __shared__ __align__(16) float raw[3][CK][TN];            // 12 KB
    __shared__ __align__(16) unsigned short xsh[TN][18];      // 2.25 KB
    __shared__ __align__(16) unsigned short xsl[TN][18];      // 2.25 KB
    __shared__ __align__(16) unsigned short wsh[3][R][24];    // 4.5 KB
    __shared__ __align__(16) unsigned short wsl[3][R][24];    // 4.5 KB
    __shared__ float wsp_s[C];                                // 2 KB
    __shared__ float spool[C];                                // 2 KB
    __shared__ float sps[2][TN];                              // 0.5 KB

    int bx = blockIdx.x;
    int b = bx >> 4;
    int tile = bx & 15;
    int n0 = tile * TN;
    int tid = threadIdx.x, lane = tid & 31, warp = tid >> 5;
    int g = lane >> 2, tg2 = (lane & 3) * 2;
    int nb = warp * 16;              // warp's 16-n slice

    const float* xg = x + ((size_t)b * C) * HW + n0;
    unsigned int raw_base = (unsigned int)__cvta_generic_to_shared(&raw[0][0][0]);
    unsigned int wsh_base = (unsigned int)__cvta_generic_to_shared(&wsh[0][0][0]);
    unsigned int wsl_base = (unsigned int)__cvta_generic_to_shared(&wsl[0][0][0]);

    // copy chunk CC: x tile 16ch x 64n fp32 (2 segs/thread) + weights (1 seg)
#define ISSUE_CHUNK(CC)                                                        \
    {                                                                          \
        int st_ = (CC) % 3;                                                    \
        _Pragma("unroll")                                                      \
        for (int j_ = 0; j_ < 2; j_++) {                                       \
            int s_ = tid + j_ * T1;                                            \
            int ch_ = s_ >> 4;               /* 0..15 */                       \
            int nf_ = (s_ & 15) << 2;        /* float offset */                \
            const float* src_ = xg + (size_t)((CC) * CK + ch_) * HW + nf_;     \
            unsigned int dst_ = raw_base + ((st_ * CK + ch_) * TN + nf_) * 4u; \
            CP_ASYNC16(dst_, src_);                                            \
        }                                                                      \
        {                                                                      \
            int r_ = (tid & 63) >> 1, sg_ = tid & 1;                           \
            const char* wsrc_;                                                 \
            unsigned int wdst_;                                                \
            if (tid < 64) {                                                    \
                wsrc_ = (const char*)g_whi + (r_ * C + (CC) * CK) * 2 + sg_ * 16; \
                wdst_ = wsh_base + (st_ * R * 24 + r_ * 24) * 2u + sg_ * 16u;  \
            } else {                                                           \
                wsrc_ = (const char*)g_wlo + (r_ * C + (CC) * CK) * 2 + sg_ * 16; \
                wdst_ = wsl_base + (st_ * R * 24 + r_ * 24) * 2u + sg_ * 16u;  \
            }                                                                  \
            CP_ASYNC16(wdst_, wsrc_);                                          \
        }                                                                      \
    }

    ISSUE_CHUNK(0) CP_COMMIT();
    ISSUE_CHUNK(1) CP_COMMIT();

    for (int idx = tid; idx < C; idx += T1) wsp_s[idx] = w_sp[idx];

    float acc[4][4];                 // [r-tile rbi][d0..d3]
#pragma unroll
    for (int i = 0; i < 4; i++)
#pragma unroll
        for (int j = 0; j < 4; j++) acc[i][j] = 0.f;
    float sp = 0.f;
    int sp_n = tid & 63, sp_ch = tid >> 6;   // spatial duty: 2 threads per n

    for (int cc = 0; cc < NCHUNK; cc++) {
        int buf = cc % 3;
        CP_WAIT1();
        __syncthreads();   // raw/ws for cc visible; cc-1 mma fully done

        // prefetch cc+2: its stage != stages read in cc and cc+1 (race-free)
        if (cc + 2 < NCHUNK) ISSUE_CHUNK(cc + 2)
        CP_COMMIT();       // (possibly empty) keeps group counting aligned

        // duty 1: pooled partial per channel (warp-owned, 4 chains/warp)
#pragma unroll
        for (int j = 0; j < 4; j++) {
            int k = warp + j * 4;
            float t = raw[buf][k][lane] + raw[buf][k][lane + 32];
            t += __shfl_xor_sync(0xffffffffu, t, 16);
            t += __shfl_xor_sync(0xffffffffu, t, 8);
            t += __shfl_xor_sync(0xffffffffu, t, 4);
            t += __shfl_xor_sync(0xffffffffu, t, 2);
            t += __shfl_xor_sync(0xffffffffu, t, 1);
            if (lane == 0) spool[cc * CK + k] = t;
        }
        // duty 2: spatial logits (thread owns n, half the channels)
#pragma unroll
        for (int j = 0; j < 8; j++) {
            int k = sp_ch * 8 + j;
            sp = fmaf(wsp_s[cc * CK + k], raw[buf][k][sp_n], sp);
        }
        // convert + transpose: raw[c][n] fp32 -> xsh/xsl[n][c] bf16 pairs
        {
            int n = tid & 63;
            int cp0 = (tid >> 6) * 2;    // 0 or 2
#pragma unroll
            for (int j = 0; j < 4; j++) {
                int c = cp0 + j * 4;
                float v0 = raw[buf][c][n];
                float v1 = raw[buf][c + 1][n];
                __nv_bfloat16 h0 = __float2bfloat16(v0);
                __nv_bfloat16 h1 = __float2bfloat16(v1);
                __nv_bfloat16 l0 = __float2bfloat16(v0 - __bfloat162float(h0));
                __nv_bfloat16 l1 = __float2bfloat16(v1 - __bfloat162float(h1));
                *(unsigned int*)&xsh[n][c] =
                    ((unsigned int)__bfloat16_as_ushort(h1) << 16) |
                    __bfloat16_as_ushort(h0);
                *(unsigned int*)&xsl[n][c] =
                    ((unsigned int)__bfloat16_as_ushort(l1) << 16) |
                    __bfloat16_as_ushort(l0);
            }
        }
        __syncthreads();   // xs ready

        // mma: single k16-step; A = xT row-major, B = w^T col-major
        {
            unsigned int ah0 = *(const unsigned int*)&xsh[nb + g][tg2];
            unsigned int ah1 = *(const unsigned int*)&xsh[nb + g + 8][tg2];
            unsigned int ah2 = *(const unsigned int*)&xsh[nb + g][8 + tg2];
            unsigned int ah3 = *(const unsigned int*)&xsh[nb + g + 8][8 + tg2];
            unsigned int al0 = *(const unsigned int*)&xsl[nb + g][tg2];
            unsigned int al1 = *(const unsigned int*)&xsl[nb + g + 8][tg2];
            unsigned int al2 = *(const unsigned int*)&xsl[nb + g][8 + tg2];
            unsigned int al3 = *(const unsigned int*)&xsl[nb + g + 8][8 + tg2];
#pragma unroll
            for (int rbi = 0; rbi < 4; rbi++) {
                int rr = rbi * 8 + g;
                unsigned int bh0 = *(const unsigned int*)&wsh[buf][rr][tg2];
                unsigned int bh1 = *(const unsigned int*)&wsh[buf][rr][8 + tg2];
                unsigned int bl0 = *(const unsigned int*)&wsl[buf][rr][tg2];
                unsigned int bl1 = *(const unsigned int*)&wsl[buf][rr][8 + tg2];
                MMA_BF16(acc[rbi], ah0, ah1, ah2, ah3, bh0, bh1);
                MMA_BF16(acc[rbi], al0, al1, al2, al3, bh0, bh1);
                MMA_BF16(acc[rbi], ah0, ah1, ah2, ah3, bl0, bl1);
            }
        }
    }
#undef ISSUE_CHUNK

    // epilogue: D[n][r] fragments -> g_featT (float2 per d-pair)
    {
        size_t nbase = (size_t)b * HW + n0 + nb;
#pragma unroll
        for (int rbi = 0; rbi < 4; rbi++) {
            *(float2*)&g_featT[(nbase + g) * R + rbi * 8 + tg2] =
                make_float2(acc[rbi][0], acc[rbi][1]);
            *(float2*)&g_featT[(nbase + g + 8) * R + rbi * 8 + tg2] =
                make_float2(acc[rbi][2], acc[rbi][3]);
        }
    }

    // combine the two spatial halves; store side products
    sps[sp_ch][sp_n] = sp;
    __syncthreads();
    if (tid < TN)
        g_sp[(size_t)b * HW + n0 + tid] = sps[0][tid] + sps[1][tid];
    for (int idx = tid; idx < C; idx += T1)
        g_poolpart[((size_t)(b * NSLOT) + tile) * C + idx] = spool[idx];
}

// ============================================================================
// Pass 2a: raw Gram partials from featT. CTA = (b, n-quarter), 256 threads.
// ============================================================================
__global__ __launch_bounds__(256) void pass2a() {
    __shared__ __align__(16) float fcT[256][36];
    int b = blockIdx.x >> 2;
    int q = blockIdx.x & 3;
    int tid = threadIdx.x;

    const float* src = g_featT + ((size_t)b * HW + q * 256) * R;
    for (int it = 0; it < 32; it++) {            // 8192 elems, coalesced
        int idx = tid + it * 256;
        fcT[idx >> 5][idx & 31] = src[idx];
    }
    __syncthreads();

    int my_r = tid >> 3;
    int s0 = (tid & 7) << 2;
    float g4[4] = {0.f, 0.f, 0.f, 0.f};
#pragma unroll 8
    for (int n = 0; n < 256; n++) {
        float fr = fcT[n][my_r];
        float4 fs = *(const float4*)&fcT[n][s0];
        g4[0] = fmaf(fr, fs.x, g4[0]);
        g4[1] = fmaf(fr, fs.y, g4[1]);
        g4[2] = fmaf(fr, fs.z, g4[2]);
        g4[3] = fmaf(fr, fs.w, g4[3]);
    }
    *(float4*)&g_covpart[((size_t)(b * 4 + q)) * (R * R) + my_r * R + s0] =
        make_float4(g4[0], g4[1], g4[2], g4[3]);
}

// ============================================================================
// Pass 2b: per-batch small work: pooled -> MLP (g_ca) + mu; cov assembly;
// power iteration. Writes g_v / g_c0. (att projection moved to pass_att.)
// ============================================================================
__global__ __launch_bounds__(256) void pass2b(const float* __restrict__ w_fc1,
                                              const float* __restrict__ b_fc1,
                                              const float* __restrict__ w_fc2,
                                              const float* __restrict__ b_fc2,
                                              const float* __restrict__ w_eig,
                                              const float* __restrict__ v0) {
    __shared__ float s_pool[C];
    __shared__ float s_mu[R];
    __shared__ float s_ca1[R];
    __shared__ float s_cov[R * R];

    int b = blockIdx.x;
    int tid = threadIdx.x, lane = tid & 31, warp = tid >> 5;

    // 1. pooled = sum of 16 tile partials / HW
    for (int c = tid; c < C; c += 256) {
        float s = 0.f;
#pragma unroll
        for (int k = 0; k < NSLOT; k++) s += g_poolpart[((size_t)b * NSLOT + k) * C + c];
        s_pool[c] = s * (1.0f / HW);
    }
    __syncthreads();

    // 2. ca1 = relu(pooled @ w_fc1^T + b_fc1); mu = w_eig @ pooled (fp32)
    for (int k = 0; k < 4; k++) {
        int r = warp + k * 8;
        float s1 = 0.f, s2 = 0.f;
        for (int c = lane; c < C; c += 32) {
            float p = s_pool[c];
            s1 = fmaf(p, w_fc1[r * C + c], s1);
            s2 = fmaf(p, w_eig[r * C + c], s2);
        }
        for (int o = 16; o > 0; o >>= 1) {
            s1 += __shfl_xor_sync(0xffffffffu, s1, o);
            s2 += __shfl_xor_sync(0xffffffffu, s2, o);
        }
        if (lane == 0) {
            s_ca1[r] = fmaxf(s1 + b_fc1[r], 0.f);
            s_mu[r] = s2;
        }
    }
    __syncthreads();

    // 3. channel attention: sigmoid(ca1 @ w_fc2^T + b_fc2)
    for (int c = tid; c < C; c += 256) {
        float a = b_fc2[c];
#pragma unroll
        for (int r = 0; r < R; r++) a = fmaf(s_ca1[r], w_fc2[c * R + r], a);
        g_ca[(size_t)b * C + c] = 1.f / (1.f + expf(-a));
    }

    // 4. cov = (sum_q G_q - HW*mu*mu^T)/(HW-1) + 1e-5 I
    for (int e0 = tid * 4; e0 < R * R; e0 += 256 * 4) {
#pragma unroll
        for (int i = 0; i < 4; i++) {
            int e = e0 + i;
            int r = e >> 5, s = e & 31;
            float gg = 0.f;
#pragma unroll
            for (int q = 0; q < 4; q++)
                gg += g_covpart[((size_t)(b * 4 + q)) * (R * R) + e];
            float v = (gg - (float)HW * s_mu[r] * s_mu[s]) * (1.0f / (HW - 1));
            if (r == s) v += 1e-5f;
            s_cov[e] = v;
        }
    }
    __syncthreads();

    // 5. power iteration (warp 0); write v and c0 = v.mu
    if (warp == 0) {
        float v = v0[b * R + lane];
        float nr = v * v;
        for (int o = 16; o > 0; o >>= 1) nr += __shfl_xor_sync(0xffffffffu, nr, o);
        v = v / sqrtf(nr);
        for (int it = 0; it < 5; it++) {
            float nv = 0.f;
#pragma unroll
            for (int s = 0; s < R; s++)
                nv = fmaf(s_cov[s * R + lane], __shfl_sync(0xffffffffu, v, s), nv);
            float nn = nv * nv;
            for (int o = 16; o > 0; o >>= 1) nn += __shfl_xor_sync(0xffffffffu, nn, o);
            v = nv / (sqrtf(nn) + 1e-10f);
        }
        g_v[b * R + lane] = v;
        float c0 = v * s_mu[lane];
        for (int o = 16; o > 0; o >>= 1) c0 += __shfl_xor_sync(0xffffffffu, c0, o);
        if (lane == 0) g_c0[b] = c0;
    }
}

// ============================================================================
// pass_att: attv = v . featT[n] - c0. Grid B*8 (512 CTAs), 128 threads,
// one n per thread (warp reads 4 KB contiguous). Block min/max -> partials.
// ============================================================================
__global__ __launch_bounds__(T1) void pass_att() {
    __shared__ float s_v[R];
    __shared__ float s_mn[4], s_mx[4];
    int b = blockIdx.x >> 3;
    int tile = blockIdx.x & 7;
    int tid = threadIdx.x, lane = tid & 31, warp = tid >> 5;
    int n = tile * 128 + tid;

    if (tid < R) s_v[tid] = g_v[b * R + tid];
    __syncthreads();

    const float4* fp = (const float4*)&g_featT[((size_t)b * HW + n) * R];
    float a = 0.f;
#pragma unroll
    for (int q = 0; q < 8; q++) {
        float4 f = fp[q];
        a = fmaf(s_v[q * 4 + 0], f.x, a);
        a = fmaf(s_v[q * 4 + 1], f.y, a);
        a = fmaf(s_v[q * 4 + 2], f.z, a);
        a = fmaf(s_v[q * 4 + 3], f.w, a);
    }
    float attv = a - g_c0[b];
    g_attraw[(size_t)b * HW + n] = attv;

    float mn = attv, mx = attv;
    for (int o = 16; o > 0; o >>= 1) {
        mn = fminf(mn, __shfl_xor_sync(0xffffffffu, mn, o));
        mx = fmaxf(mx, __shfl_xor_sync(0xffffffffu, mx, o));
    }
    if (lane == 0) { s_mn[warp] = mn; s_mx[warp] = mx; }
    __syncthreads();
    if (tid == 0) {
        float a0 = fminf(fminf(s_mn[0], s_mn[1]), fminf(s_mn[2], s_mn[3]));
        float m0 = fmaxf(fmaxf(s_mx[0], s_mx[1]), fmaxf(s_mx[2], s_mx[3]));
        g_mn[b * 8 + tile] = a0;
        g_mx[b * 8 + tile] = m0;
    }
}

// ============================================================================
// pass_fin: finalize att = sigmoid((attv-amin)/denom) * sigmoid(sp + bsp).
// Grid B, 256 threads, 4 n per thread.
// ============================================================================
__global__ __launch_bounds__(256) void pass_fin(const float* __restrict__ b_sp) {
    __shared__ float s_amin, s_denom;
    int b = blockIdx.x;
    int tid = threadIdx.x;
    if (tid == 0) {
        float a = g_mn[b * 8], m = g_mx[b * 8];
#pragma unroll
        for (int k = 1; k < 8; k++) {
            a = fminf(a, g_mn[b * 8 + k]);
            m = fmaxf(m, g_mx[b * 8 + k]);
        }
        s_amin = a;
        s_denom = (m - a) + 1e-10f;
    }
    __syncthreads();
    float amin = s_amin, denom = s_denom;
    float bspv = b_sp[0];
#pragma unroll
    for (int k = 0; k < 4; k++) {
        int n = k * 256 + tid;
        float attv = g_attraw[(size_t)b * HW + n];
        float e = 1.f / (1.f + expf(-((attv - amin) / denom)));
        float sl = g_sp[(size_t)b * HW + n] + bspv;
        float sa = 1.f / (1.f + expf(-sl));
        g_att[(size_t)b * HW + n] = e * sa;
    }
}

// ============================================================================
// Pass 3: out = x * (1 + ca[b,c] * att[b,n])  (2x float4 per thread)
// ============================================================================
__global__ __launch_bounds__(256) void pass3(const float* __restrict__ x,
                                             float* __restrict__ out) {
    unsigned int base = blockIdx.x * 512u + threadIdx.x;
#pragma unroll
    for (int u = 0; u < 2; u++) {
        unsigned int i = base + u * 256u;      // float4 index
        int n4 = i & 255;                      // HW/4 = 256
        int c = (i >> 8) & (C - 1);
        int b = i >> 17;
        float ca = g_ca[b * C + c];
        float4 at = ((const float4*)g_att)[(size_t)b * (HW / 4) + n4];
        float4 xv = ((const float4*)x)[i];
        float4 o;
        o.x = fmaf(xv.x, ca * at.x, xv.x);
        o.y = fmaf(xv.y, ca * at.y, xv.y);
        o.z = fmaf(xv.z, ca * at.z, xv.z);
        o.w = fmaf(xv.w, ca * at.w, xv.w);
        ((float4*)out)[i] = o;
    }
}

extern "C" void kernel_launch(void* const* d_in, const int* in_sizes, int n_in,
                              void* d_out, int out_size) {
    const float* x     = (const float*)d_in[0];
    const float* w_fc1 = (const float*)d_in[1];
    const float* b_fc1 = (const float*)d_in[2];
    const float* w_fc2 = (const float*)d_in[3];
    const float* b_fc2 = (const float*)d_in[4];
    const float* w_eig = (const float*)d_in[5];
    /* d_in[6] = b_eig: cancels in feat_c and in mu -> unused */
    const float* w_sp  = (const float*)d_in[7];
    const float* b_sp  = (const float*)d_in[8];
    const float* v0    = (const float*)d_in[9];
    float* out = (float*)d_out;

    pass0<<<R * C / 256, 256>>>(w_eig);
    pass1<<<B * NTILE, T1>>>(x, w_sp);
    pass2a<<<B * 4, 256>>>();
    pass2b<<<B, 256>>>(w_fc1, b_fc1, w_fc2, b_fc2, w_eig, v0);
    pass_att<<<B * 8, T1>>>();
    pass_fin<<<B, 256>>>(b_sp);
    pass3<<<(B * C * HW / 4) / 512, 256>>>(x, out);
}

// round 15
// speedup vs baseline: 1.1268x; 1.0299x over previous
#include <cuda_runtime.h>
#include <cuda_bf16.h>
#include <math.h>

#define B 64
#define C 512
#define HW 1024
#define R 32
#define T1 128
#define TN 64          // n per pass1 tile
#define NTILE 16       // HW / TN
#define NSLOT 16       // one pooled partial per tile
#define CK 16          // channels per chunk
#define NCHUNK 32      // C / CK

// cp.async helpers (Ampere+)
#define CP_ASYNC16(dst_u32, src_ptr) \
    asm volatile("cp.async.cg.shared.global [%0], [%1], 16;" \
                 :: "r"(dst_u32), "l"(src_ptr))
#define CP_COMMIT() asm volatile("cp.async.commit_group;" ::: "memory")
#define CP_WAIT1()  asm volatile("cp.async.wait_group 1;" ::: "memory")

// m16n8k16 row.col bf16 mma, fp32 accumulate
#define MMA_BF16(D, A0, A1, A2, A3, B0, B1)                                    \
    asm volatile(                                                              \
        "mma.sync.aligned.m16n8k16.row.col.f32.bf16.bf16.f32 "                 \
        "{%0,%1,%2,%3}, {%4,%5,%6,%7}, {%8,%9}, {%0,%1,%2,%3};"                \
        : "+f"(D[0]), "+f"(D[1]), "+f"(D[2]), "+f"(D[3])                       \
        : "r"(A0), "r"(A1), "r"(A2), "r"(A3), "r"(B0), "r"(B1))

// ---------------- scratch (device globals: no allocation allowed) -------------
__device__ float g_featT[B * HW * R];       // 8 MB  featT[b][n][r] (no bias)
__device__ __align__(256) __nv_bfloat16 g_whi[R * C];   // 32 KB weight hi
__device__ __align__(256) __nv_bfloat16 g_wlo[R * C];   // 32 KB weight lo
__device__ float g_poolpart[B * NSLOT * C]; // 2 MB   partial sums for pooled
__device__ float g_covpart[B * 4 * R * R];  // 1 MB   raw Gram partials
__device__ float g_sp[B * HW];              // 256 KB spatial logits (no bias)
__device__ float g_ca[B * C];               // 128 KB channel attention
__device__ float g_ca1[B * R];              // MLP hidden layer (relu)
__device__ float g_att[B * HW];             // 256 KB final attention product
__device__ float g_attraw[B * HW];          // 256 KB raw attv values
__device__ float g_v[B * R];                // eigenvector per batch
__device__ float g_c0[B];                   // v . mu per batch
__device__ float g_mn[B * 8], g_mx[B * 8];  // per-tile min/max partials

// ============================================================================
// Pass 0: split w_eig into bf16 hi/lo (bf16x3 decomposition), layout [r][c].
// ============================================================================
__global__ __launch_bounds__(256) void pass0(const float* __restrict__ w_eig) {
    int i = blockIdx.x * 256 + threadIdx.x;   // grid 64 -> 16384
    float v = w_eig[i];
    __nv_bfloat16 h = __float2bfloat16(v);
    g_whi[i] = h;
    g_wlo[i] = __float2bfloat16(v - __bfloat162float(h));
}

// ============================================================================
// Pass 1: bf16x3 tensor-core GEMM -> featT[b][n][r]. (unchanged from R14)
// ============================================================================
__global__ __launch_bounds__(T1) void pass1(const float* __restrict__ x,
                                            const float* __restrict__ w_sp) {
    __shared__ __align__(16) float raw[3][CK][TN];            // 12 KB
    __shared__ __align__(16) unsigned short xsh[TN][18];      // 2.25 KB
    __shared__ __align__(16) unsigned short xsl[TN][18];      // 2.25 KB
    __shared__ __align__(16) unsigned short wsh[3][R][24];    // 4.5 KB
    __shared__ __align__(16) unsigned short wsl[3][R][24];    // 4.5 KB
    __shared__ float wsp_s[C];                                // 2 KB
    __shared__ float spool[C];                                // 2 KB
    __shared__ float sps[2][TN];                              // 0.5 KB

    int bx = blockIdx.x;
    int b = bx >> 4;
    int tile = bx & 15;
    int n0 = tile * TN;
    int tid = threadIdx.x, lane = tid & 31, warp = tid >> 5;
    int g = lane >> 2, tg2 = (lane & 3) * 2;
    int nb = warp * 16;              // warp's 16-n slice

    const float* xg = x + ((size_t)b * C) * HW + n0;
    unsigned int raw_base = (unsigned int)__cvta_generic_to_shared(&raw[0][0][0]);
    unsigned int wsh_base = (unsigned int)__cvta_generic_to_shared(&wsh[0][0][0]);
    unsigned int wsl_base = (unsigned int)__cvta_generic_to_shared(&wsl[0][0][0]);

#define ISSUE_CHUNK(CC)                                                        \
    {                                                                          \
        int st_ = (CC) % 3;                                                    \
        _Pragma("unroll")                                                      \
        for (int j_ = 0; j_ < 2; j_++) {                                       \
            int s_ = tid + j_ * T1;                                            \
            int ch_ = s_ >> 4;               /* 0..15 */                       \
            int nf_ = (s_ & 15) << 2;        /* float offset */                \
            const float* src_ = xg + (size_t)((CC) * CK + ch_) * HW + nf_;     \
            unsigned int dst_ = raw_base + ((st_ * CK + ch_) * TN + nf_) * 4u; \
            CP_ASYNC16(dst_, src_);                                            \
        }                                                                      \
        {                                                                      \
            int r_ = (tid & 63) >> 1, sg_ = tid & 1;                           \
            const char* wsrc_;                                                 \
            unsigned int wdst_;                                                \
            if (tid < 64) {                                                    \
                wsrc_ = (const char*)g_whi + (r_ * C + (CC) * CK) * 2 + sg_ * 16; \
                wdst_ = wsh_base + (st_ * R * 24 + r_ * 24) * 2u + sg_ * 16u;  \
            } else {                                                           \
                wsrc_ = (const char*)g_wlo + (r_ * C + (CC) * CK) * 2 + sg_ * 16; \
                wdst_ = wsl_base + (st_ * R * 24 + r_ * 24) * 2u + sg_ * 16u;  \
            }                                                                  \
            CP_ASYNC16(wdst_, wsrc_);                                          \
        }                                                                      \
    }

    ISSUE_CHUNK(0) CP_COMMIT();
    ISSUE_CHUNK(1) CP_COMMIT();

    for (int idx = tid; idx < C; idx += T1) wsp_s[idx] = w_sp[idx];

    float acc[4][4];
#pragma unroll
    for (int i = 0; i < 4; i++)
#pragma unroll
        for (int j = 0; j < 4; j++) acc[i][j] = 0.f;
    float sp = 0.f;
    int sp_n = tid & 63, sp_ch = tid >> 6;

    for (int cc = 0; cc < NCHUNK; cc++) {
        int buf = cc % 3;
        CP_WAIT1();
        __syncthreads();

        if (cc + 2 < NCHUNK) ISSUE_CHUNK(cc + 2)
        CP_COMMIT();

#pragma unroll
        for (int j = 0; j < 4; j++) {
            int k = warp + j * 4;
            float t = raw[buf][k][lane] + raw[buf][k][lane + 32];
            t += __shfl_xor_sync(0xffffffffu, t, 16);
            t += __shfl_xor_sync(0xffffffffu, t, 8);
            t += __shfl_xor_sync(0xffffffffu, t, 4);
            t += __shfl_xor_sync(0xffffffffu, t, 2);
            t += __shfl_xor_sync(0xffffffffu, t, 1);
            if (lane == 0) spool[cc * CK + k] = t;
        }
#pragma unroll
        for (int j = 0; j < 8; j++) {
            int k = sp_ch * 8 + j;
            sp = fmaf(wsp_s[cc * CK + k], raw[buf][k][sp_n], sp);
        }
        {
            int n = tid & 63;
            int cp0 = (tid >> 6) * 2;
#pragma unroll
            for (int j = 0; j < 4; j++) {
                int c = cp0 + j * 4;
                float v0 = raw[buf][c][n];
                float v1 = raw[buf][c + 1][n];
                __nv_bfloat16 h0 = __float2bfloat16(v0);
                __nv_bfloat16 h1 = __float2bfloat16(v1);
                __nv_bfloat16 l0 = __float2bfloat16(v0 - __bfloat162float(h0));
                __nv_bfloat16 l1 = __float2bfloat16(v1 - __bfloat162float(h1));
                *(unsigned int*)&xsh[n][c] =
                    ((unsigned int)__bfloat16_as_ushort(h1) << 16) |
                    __bfloat16_as_ushort(h0);
                *(unsigned int*)&xsl[n][c] =
                    ((unsigned int)__bfloat16_as_ushort(l1) << 16) |
                    __bfloat16_as_ushort(l0);
            }
        }
        __syncthreads();

        {
            unsigned int ah0 = *(const unsigned int*)&xsh[nb + g][tg2];
            unsigned int ah1 = *(const unsigned int*)&xsh[nb + g + 8][tg2];
            unsigned int ah2 = *(const unsigned int*)&xsh[nb + g][8 + tg2];
            unsigned int ah3 = *(const unsigned int*)&xsh[nb + g + 8][8 + tg2];
            unsigned int al0 = *(const unsigned int*)&xsl[nb + g][tg2];
            unsigned int al1 = *(const unsigned int*)&xsl[nb + g + 8][tg2];
            unsigned int al2 = *(const unsigned int*)&xsl[nb + g][8 + tg2];
            unsigned int al3 = *(const unsigned int*)&xsl[nb + g + 8][8 + tg2];
#pragma unroll
            for (int rbi = 0; rbi < 4; rbi++) {
                int rr = rbi * 8 + g;
                unsigned int bh0 = *(const unsigned int*)&wsh[buf][rr][tg2];
                unsigned int bh1 = *(const unsigned int*)&wsh[buf][rr][8 + tg2];
                unsigned int bl0 = *(const unsigned int*)&wsl[buf][rr][tg2];
                unsigned int bl1 = *(const unsigned int*)&wsl[buf][rr][8 + tg2];
                MMA_BF16(acc[rbi], ah0, ah1, ah2, ah3, bh0, bh1);
                MMA_BF16(acc[rbi], al0, al1, al2, al3, bh0, bh1);
                MMA_BF16(acc[rbi], ah0, ah1, ah2, ah3, bl0, bl1);
            }
        }
    }
#undef ISSUE_CHUNK

    {
        size_t nbase = (size_t)b * HW + n0 + nb;
#pragma unroll
        for (int rbi = 0; rbi < 4; rbi++) {
            *(float2*)&g_featT[(nbase + g) * R + rbi * 8 + tg2] =
                make_float2(acc[rbi][0], acc[rbi][1]);
            *(float2*)&g_featT[(nbase + g + 8) * R + rbi * 8 + tg2] =
                make_float2(acc[rbi][2], acc[rbi][3]);
        }
    }

    sps[sp_ch][sp_n] = sp;
    __syncthreads();
    if (tid < TN)
        g_sp[(size_t)b * HW + n0 + tid] = sps[0][tid] + sps[1][tid];
    for (int idx = tid; idx < C; idx += T1)
        g_poolpart[((size_t)(b * NSLOT) + tile) * C + idx] = spool[idx];
}

// ============================================================================
// Pass 2a: raw Gram partials from featT. (unchanged from R14)
// ============================================================================
__global__ __launch_bounds__(256) void pass2a() {
    __shared__ __align__(16) float fcT[256][36];
    int b = blockIdx.x >> 2;
    int q = blockIdx.x & 3;
    int tid = threadIdx.x;

    const float* src = g_featT + ((size_t)b * HW + q * 256) * R;
    for (int it = 0; it < 32; it++) {
        int idx = tid + it * 256;
        fcT[idx >> 5][idx & 31] = src[idx];
    }
    __syncthreads();

    int my_r = tid >> 3;
    int s0 = (tid & 7) << 2;
    float g4[4] = {0.f, 0.f, 0.f, 0.f};
#pragma unroll 8
    for (int n = 0; n < 256; n++) {
        float fr = fcT[n][my_r];
        float4 fs = *(const float4*)&fcT[n][s0];
        g4[0] = fmaf(fr, fs.x, g4[0]);
        g4[1] = fmaf(fr, fs.y, g4[1]);
        g4[2] = fmaf(fr, fs.z, g4[2]);
        g4[3] = fmaf(fr, fs.w, g4[3]);
    }
    *(float4*)&g_covpart[((size_t)(b * 4 + q)) * (R * R) + my_r * R + s0] =
        make_float4(g4[0], g4[1], g4[2], g4[3]);
}

// ============================================================================
// Pass 2b: per-batch: pooled -> ca1 + mu (FULLY UNROLLED batched loads);
// cov assembly; power iteration. Writes g_ca1 / g_v / g_c0.
// Channel attention moved to pass_ca (parallel).
// ============================================================================
__global__ __launch_bounds__(256) void pass2b(const float* __restrict__ w_fc1,
                                              const float* __restrict__ b_fc1,
                                              const float* __restrict__ w_eig,
                                              const float* __restrict__ v0) {
    __shared__ float s_pool[C];
    __shared__ float s_mu[R];
    __shared__ float s_cov[R * R];

    int b = blockIdx.x;
    int tid = threadIdx.x, lane = tid & 31, warp = tid >> 5;

    // 1. pooled = sum of 16 tile partials / HW (loads batched by unroll)
#pragma unroll
    for (int cb = 0; cb < 2; cb++) {
        int c = tid + cb * 256;
        float s = 0.f;
#pragma unroll
        for (int k = 0; k < NSLOT; k++) s += g_poolpart[((size_t)b * NSLOT + k) * C + c];
        s_pool[c] = s * (1.0f / HW);
    }
    __syncthreads();

    // 2. ca1 = relu(pooled @ w_fc1^T + b_fc1); mu = w_eig @ pooled.
    //    Fully unrolled 16-iteration loops: 32 independent LDGs in flight.
#pragma unroll
    for (int k = 0; k < 4; k++) {
        int r = warp + k * 8;
        float s1 = 0.f, s2 = 0.f;
#pragma unroll
        for (int ci = 0; ci < 16; ci++) {
            int c = lane + ci * 32;
            float p = s_pool[c];
            s1 = fmaf(p, w_fc1[r * C + c], s1);
            s2 = fmaf(p, w_eig[r * C + c], s2);
        }
#pragma unroll
        for (int o = 16; o > 0; o >>= 1) {
            s1 += __shfl_xor_sync(0xffffffffu, s1, o);
            s2 += __shfl_xor_sync(0xffffffffu, s2, o);
        }
        if (lane == 0) {
            g_ca1[b * R + r] = fmaxf(s1 + b_fc1[r], 0.f);
            s_mu[r] = s2;
        }
    }
    __syncthreads();

    // 3. cov = (sum_q G_q - HW*mu*mu^T)/(HW-1) + 1e-5 I
#pragma unroll
    for (int i = 0; i < 4; i++) {
        int e = tid * 4 + i;
        if (e < R * R) {
            int r = e >> 5, s = e & 31;
            float gg = 0.f;
#pragma unroll
            for (int q = 0; q < 4; q++)
                gg += g_covpart[((size_t)(b * 4 + q)) * (R * R) + e];
            float v = (gg - (float)HW * s_mu[r] * s_mu[s]) * (1.0f / (HW - 1));
            if (r == s) v += 1e-5f;
            s_cov[e] = v;
        }
    }
    __syncthreads();

    // 4. power iteration (warp 0); write v and c0 = v.mu
    if (warp == 0) {
        float v = v0[b * R + lane];
        float nr = v * v;
#pragma unroll
        for (int o = 16; o > 0; o >>= 1) nr += __shfl_xor_sync(0xffffffffu, nr, o);
        v = v / sqrtf(nr);
#pragma unroll
        for (int it = 0; it < 5; it++) {
            float nv = 0.f;
#pragma unroll
            for (int s = 0; s < R; s++)
                nv = fmaf(s_cov[s * R + lane], __shfl_sync(0xffffffffu, v, s), nv);
            float nn = nv * nv;
#pragma unroll
            for (int o = 16; o > 0; o >>= 1) nn += __shfl_xor_sync(0xffffffffu, nn, o);
            v = nv / (sqrtf(nn) + 1e-10f);
        }
        g_v[b * R + lane] = v;
        float c0 = v * s_mu[lane];
#pragma unroll
        for (int o = 16; o > 0; o >>= 1) c0 += __shfl_xor_sync(0xffffffffu, c0, o);
        if (lane == 0) g_c0[b] = c0;
    }
}

// ============================================================================
// pass_ca: channel attention, parallel. Grid B*2 (128 CTAs), 256 threads,
// one c per thread. ca1[b] staged in smem; 8 float4 loads of w_fc2 row.
// ============================================================================
__global__ __launch_bounds__(256) void pass_ca(const float* __restrict__ w_fc2,
                                               const float* __restrict__ b_fc2) {
    __shared__ float s_ca1[R];
    int b = blockIdx.x >> 1;
    int c = (blockIdx.x & 1) * 256 + threadIdx.x;
    if (threadIdx.x < R) s_ca1[threadIdx.x] = g_ca1[b * R + threadIdx.x];
    __syncthreads();

    const float4* wrow = (const float4*)&w_fc2[c * R];
    float a = b_fc2[c];
#pragma unroll
    for (int q = 0; q < 8; q++) {
        float4 w = wrow[q];
        a = fmaf(s_ca1[q * 4 + 0], w.x, a);
        a = fmaf(s_ca1[q * 4 + 1], w.y, a);
        a = fmaf(s_ca1[q * 4 + 2], w.z, a);
        a = fmaf(s_ca1[q * 4 + 3], w.w, a);
    }
    g_ca[(size_t)b * C + c] = 1.f / (1.f + expf(-a));
}

// ============================================================================
// pass_att: attv = v . featT[n] - c0. (unchanged from R14)
// ============================================================================
__global__ __launch_bounds__(T1) void pass_att() {
    __shared__ float s_v[R];
    __shared__ float s_mn[4], s_mx[4];
    int b = blockIdx.x >> 3;
    int tile = blockIdx.x & 7;
    int tid = threadIdx.x, lane = tid & 31, warp = tid >> 5;
    int n = tile * 128 + tid;

    if (tid < R) s_v[tid] = g_v[b * R + tid];
    __syncthreads();

    const float4* fp = (const float4*)&g_featT[((size_t)b * HW + n) * R];
    float a = 0.f;
#pragma unroll
    for (int q = 0; q < 8; q++) {
        float4 f = fp[q];
        a = fmaf(s_v[q * 4 + 0], f.x, a);
        a = fmaf(s_v[q * 4 + 1], f.y, a);
        a = fmaf(s_v[q * 4 + 2], f.z, a);
        a = fmaf(s_v[q * 4 + 3], f.w, a);
    }
    float attv = a - g_c0[b];
    g_attraw[(size_t)b * HW + n] = attv;

    float mn = attv, mx = attv;
#pragma unroll
    for (int o = 16; o > 0; o >>= 1) {
        mn = fminf(mn, __shfl_xor_sync(0xffffffffu, mn, o));
        mx = fmaxf(mx, __shfl_xor_sync(0xffffffffu, mx, o));
    }
    if (lane == 0) { s_mn[warp] = mn; s_mx[warp] = mx; }
    __syncthreads();
    if (tid == 0) {
        float a0 = fminf(fminf(s_mn[0], s_mn[1]), fminf(s_mn[2], s_mn[3]));
        float m0 = fmaxf(fmaxf(s_mx[0], s_mx[1]), fmaxf(s_mx[2], s_mx[3]));
        g_mn[b * 8 + tile] = a0;
        g_mx[b * 8 + tile] = m0;
    }
}

// ============================================================================
// pass_fin: finalize att. (unchanged from R14)
// ============================================================================
__global__ __launch_bounds__(256) void pass_fin(const float* __restrict__ b_sp) {
    __shared__ float s_amin, s_denom;
    int b = blockIdx.x;
    int tid = threadIdx.x;
    if (tid == 0) {
        float a = g_mn[b * 8], m = g_mx[b * 8];
#pragma unroll
        for (int k = 1; k < 8; k++) {
            a = fminf(a, g_mn[b * 8 + k]);
            m = fmaxf(m, g_mx[b * 8 + k]);
        }
        s_amin = a;
        s_denom = (m - a) + 1e-10f;
    }
    __syncthreads();
    float amin = s_amin, denom = s_denom;
    float bspv = b_sp[0];
#pragma unroll
    for (int k = 0; k < 4; k++) {
        int n = k * 256 + tid;
        float attv = g_attraw[(size_t)b * HW + n];
        float e = 1.f / (1.f + expf(-((attv - amin) / denom)));
        float sl = g_sp[(size_t)b * HW + n] + bspv;
        float sa = 1.f / (1.f + expf(-sl));
        g_att[(size_t)b * HW + n] = e * sa;
    }
}

// ============================================================================
// Pass 3: out = x * (1 + ca[b,c] * att[b,n])  (unchanged from R14)
// ============================================================================
__global__ __launch_bounds__(256) void pass3(const float* __restrict__ x,
                                             float* __restrict__ out) {
    unsigned int base = blockIdx.x * 512u + threadIdx.x;
#pragma unroll
    for (int u = 0; u < 2; u++) {
        unsigned int i = base + u * 256u;      // float4 index
        int n4 = i & 255;                      // HW/4 = 256
        int c = (i >> 8) & (C - 1);
        int b = i >> 17;
        float ca = g_ca[b * C + c];
        float4 at = ((const float4*)g_att)[(size_t)b * (HW / 4) + n4];
        float4 xv = ((const float4*)x)[i];
        float4 o;
        o.x = fmaf(xv.x, ca * at.x, xv.x);
        o.y = fmaf(xv.y, ca * at.y, xv.y);
        o.z = fmaf(xv.z, ca * at.z, xv.z);
        o.w = fmaf(xv.w, ca * at.w, xv.w);
        ((float4*)out)[i] = o;
    }
}

extern "C" void kernel_launch(void* const* d_in, const int* in_sizes, int n_in,
                              void* d_out, int out_size) {
    const float* x     = (const float*)d_in[0];
    const float* w_fc1 = (const float*)d_in[1];
    const float* b_fc1 = (const float*)d_in[2];
    const float* w_fc2 = (const float*)d_in[3];
    const float* b_fc2 = (const float*)d_in[4];
    const float* w_eig = (const float*)d_in[5];
    /* d_in[6] = b_eig: cancels in feat_c and in mu -> unused */
    const float* w_sp  = (const float*)d_in[7];
    const float* b_sp  = (const float*)d_in[8];
    const float* v0    = (const float*)d_in[9];
    float* out = (float*)d_out;

    pass0<<<R * C / 256, 256>>>(w_eig);
    pass1<<<B * NTILE, T1>>>(x, w_sp);
    pass2a<<<B * 4, 256>>>();
    pass2b<<<B, 256>>>(w_fc1, b_fc1, w_eig, v0);
    pass_ca<<<B * 2, 256>>>(w_fc2, b_fc2);
    pass_att<<<B * 8, T1>>>();
    pass_fin<<<B, 256>>>(b_sp);
    pass3<<<(B * C * HW / 4) / 512, 256>>>(x, out);
}

// round 17
// speedup vs baseline: 1.1571x; 1.0269x over previous
#include <cuda_runtime.h>
#include <cuda_bf16.h>
#include <math.h>

#define B 64
#define C 512
#define HW 1024
#define R 32
#define T1 128
#define TN 64          // n per pass1 tile
#define NTILE 16       // HW / TN
#define NSLOT 16       // one pooled partial per tile
#define CK 16          // channels per chunk
#define NCHUNK 32      // C / CK

// cp.async helpers (Ampere+)
#define CP_ASYNC16(dst_u32, src_ptr) \
    asm volatile("cp.async.cg.shared.global [%0], [%1], 16;" \
                 :: "r"(dst_u32), "l"(src_ptr))
#define CP_COMMIT() asm volatile("cp.async.commit_group;" ::: "memory")
#define CP_WAIT1()  asm volatile("cp.async.wait_group 1;" ::: "memory")

// m16n8k16 row.col bf16 mma, fp32 accumulate
#define MMA_BF16(D, A0, A1, A2, A3, B0, B1)                                    \
    asm volatile(                                                              \
        "mma.sync.aligned.m16n8k16.row.col.f32.bf16.bf16.f32 "                 \
        "{%0,%1,%2,%3}, {%4,%5,%6,%7}, {%8,%9}, {%0,%1,%2,%3};"                \
        : "+f"(D[0]), "+f"(D[1]), "+f"(D[2]), "+f"(D[3])                       \
        : "r"(A0), "r"(A1), "r"(A2), "r"(A3), "r"(B0), "r"(B1))

// ---------------- scratch (device globals: no allocation allowed) -------------
__device__ float g_featT[B * HW * R];       // 8 MB  featT[b][n][r] (no bias)
__device__ __align__(256) __nv_bfloat16 g_whi[R * C];   // 32 KB weight hi
__device__ __align__(256) __nv_bfloat16 g_wlo[R * C];   // 32 KB weight lo
__device__ float g_poolpart[B * NSLOT * C]; // 2 MB   partial sums for pooled
__device__ float g_pool[B * C];             // 128 KB pooled (mean over n)
__device__ float g_covpart[B * 4 * R * R];  // 1 MB   raw Gram partials
__device__ float g_sp[B * HW];              // 256 KB spatial logits (no bias)
__device__ float g_ca[B * C];               // 128 KB channel attention
__device__ float g_ca1[B * R];              // MLP hidden layer (relu)
__device__ float g_att[B * HW];             // 256 KB final attention product
__device__ float g_v[B * R];                // eigenvector per batch
__device__ float g_c0[B];                   // v . mu per batch

// ============================================================================
// Pass 0: split w_eig into bf16 hi/lo (bf16x3 decomposition), layout [r][c].
// ============================================================================
__global__ __launch_bounds__(256) void pass0(const float* __restrict__ w_eig) {
    int i = blockIdx.x * 256 + threadIdx.x;   // grid 64 -> 16384
    float v = w_eig[i];
    __nv_bfloat16 h = __float2bfloat16(v);
    g_whi[i] = h;
    g_wlo[i] = __float2bfloat16(v - __bfloat162float(h));
}

// ============================================================================
// Pass 1: bf16x3 tensor-core GEMM -> featT[b][n][r]. (unchanged from R15)
// ============================================================================
__global__ __launch_bounds__(T1) void pass1(const float* __restrict__ x,
                                            const float* __restrict__ w_sp) {
    __shared__ __align__(16) float raw[3][CK][TN];            // 12 KB
    __shared__ __align__(16) unsigned short xsh[TN][18];      // 2.25 KB
    __shared__ __align__(16) unsigned short xsl[TN][18];      // 2.25 KB
    __shared__ __align__(16) unsigned short wsh[3][R][24];    // 4.5 KB
    __shared__ __align__(16) unsigned short wsl[3][R][24];    // 4.5 KB
    __shared__ float wsp_s[C];                                // 2 KB
    __shared__ float spool[C];                                // 2 KB
    __shared__ float sps[2][TN];                              // 0.5 KB

    int bx = blockIdx.x;
    int b = bx >> 4;
    int tile = bx & 15;
    int n0 = tile * TN;
    int tid = threadIdx.x, lane = tid & 31, warp = tid >> 5;
    int g = lane >> 2, tg2 = (lane & 3) * 2;
    int nb = warp * 16;              // warp's 16-n slice

    const float* xg = x + ((size_t)b * C) * HW + n0;
    unsigned int raw_base = (unsigned int)__cvta_generic_to_shared(&raw[0][0][0]);
    unsigned int wsh_base = (unsigned int)__cvta_generic_to_shared(&wsh[0][0][0]);
    unsigned int wsl_base = (unsigned int)__cvta_generic_to_shared(&wsl[0][0][0]);

#define ISSUE_CHUNK(CC)                                                        \
    {                                                                          \
        int st_ = (CC) % 3;                                                    \
        _Pragma("unroll")                                                      \
        for (int j_ = 0; j_ < 2; j_++) {                                       \
            int s_ = tid + j_ * T1;                                            \
            int ch_ = s_ >> 4;               /* 0..15 */                       \
            int nf_ = (s_ & 15) << 2;        /* float offset */                \
            const float* src_ = xg + (size_t)((CC) * CK + ch_) * HW + nf_;     \
            unsigned int dst_ = raw_base + ((st_ * CK + ch_) * TN + nf_) * 4u; \
            CP_ASYNC16(dst_, src_);                                            \
        }                                                                      \
        {                                                                      \
            int r_ = (tid & 63) >> 1, sg_ = tid & 1;                           \
            const char* wsrc_;                                                 \
            unsigned int wdst_;                                                \
            if (tid < 64) {                                                    \
                wsrc_ = (const char*)g_whi + (r_ * C + (CC) * CK) * 2 + sg_ * 16; \
                wdst_ = wsh_base + (st_ * R * 24 + r_ * 24) * 2u + sg_ * 16u;  \
            } else {                                                           \
                wsrc_ = (const char*)g_wlo + (r_ * C + (CC) * CK) * 2 + sg_ * 16; \
                wdst_ = wsl_base + (st_ * R * 24 + r_ * 24) * 2u + sg_ * 16u;  \
            }                                                                  \
            CP_ASYNC16(wdst_, wsrc_);                                          \
        }                                                                      \
    }

    ISSUE_CHUNK(0) CP_COMMIT();
    ISSUE_CHUNK(1) CP_COMMIT();

    for (int idx = tid; idx < C; idx += T1) wsp_s[idx] = w_sp[idx];

    float acc[4][4];
#pragma unroll
    for (int i = 0; i < 4; i++)
#pragma unroll
        for (int j = 0; j < 4; j++) acc[i][j] = 0.f;
    float sp = 0.f;
    int sp_n = tid & 63, sp_ch = tid >> 6;

    for (int cc = 0; cc < NCHUNK; cc++) {
        int buf = cc % 3;
        CP_WAIT1();
        __syncthreads();

        if (cc + 2 < NCHUNK) ISSUE_CHUNK(cc + 2)
        CP_COMMIT();

#pragma unroll
        for (int j = 0; j < 4; j++) {
            int k = warp + j * 4;
            float t = raw[buf][k][lane] + raw[buf][k][lane + 32];
            t += __shfl_xor_sync(0xffffffffu, t, 16);
            t += __shfl_xor_sync(0xffffffffu, t, 8);
            t += __shfl_xor_sync(0xffffffffu, t, 4);
            t += __shfl_xor_sync(0xffffffffu, t, 2);
            t += __shfl_xor_sync(0xffffffffu, t, 1);
            if (lane == 0) spool[cc * CK + k] = t;
        }
#pragma unroll
        for (int j = 0; j < 8; j++) {
            int k = sp_ch * 8 + j;
            sp = fmaf(wsp_s[cc * CK + k], raw[buf][k][sp_n], sp);
        }
        {
            int n = tid & 63;
            int cp0 = (tid >> 6) * 2;
#pragma unroll
            for (int j = 0; j < 4; j++) {
                int c = cp0 + j * 4;
                float v0 = raw[buf][c][n];
                float v1 = raw[buf][c + 1][n];
                __nv_bfloat16 h0 = __float2bfloat16(v0);
                __nv_bfloat16 h1 = __float2bfloat16(v1);
                __nv_bfloat16 l0 = __float2bfloat16(v0 - __bfloat162float(h0));
                __nv_bfloat16 l1 = __float2bfloat16(v1 - __bfloat162float(h1));
                *(unsigned int*)&xsh[n][c] =
                    ((unsigned int)__bfloat16_as_ushort(h1) << 16) |
                    __bfloat16_as_ushort(h0);
                *(unsigned int*)&xsl[n][c] =
                    ((unsigned int)__bfloat16_as_ushort(l1) << 16) |
                    __bfloat16_as_ushort(l0);
            }
        }
        __syncthreads();

        {
            unsigned int ah0 = *(const unsigned int*)&xsh[nb + g][tg2];
            unsigned int ah1 = *(const unsigned int*)&xsh[nb + g + 8][tg2];
            unsigned int ah2 = *(const unsigned int*)&xsh[nb + g][8 + tg2];
            unsigned int ah3 = *(const unsigned int*)&xsh[nb + g + 8][8 + tg2];
            unsigned int al0 = *(const unsigned int*)&xsl[nb + g][tg2];
            unsigned int al1 = *(const unsigned int*)&xsl[nb + g + 8][tg2];
            unsigned int al2 = *(const unsigned int*)&xsl[nb + g][8 + tg2];
            unsigned int al3 = *(const unsigned int*)&xsl[nb + g + 8][8 + tg2];
#pragma unroll
            for (int rbi = 0; rbi < 4; rbi++) {
                int rr = rbi * 8 + g;
                unsigned int bh0 = *(const unsigned int*)&wsh[buf][rr][tg2];
                unsigned int bh1 = *(const unsigned int*)&wsh[buf][rr][8 + tg2];
                unsigned int bl0 = *(const unsigned int*)&wsl[buf][rr][tg2];
                unsigned int bl1 = *(const unsigned int*)&wsl[buf][rr][8 + tg2];
                MMA_BF16(acc[rbi], ah0, ah1, ah2, ah3, bh0, bh1);
                MMA_BF16(acc[rbi], al0, al1, al2, al3, bh0, bh1);
                MMA_BF16(acc[rbi], ah0, ah1, ah2, ah3, bl0, bl1);
            }
        }
    }
#undef ISSUE_CHUNK

    {
        size_t nbase = (size_t)b * HW + n0 + nb;
#pragma unroll
        for (int rbi = 0; rbi < 4; rbi++) {
            *(float2*)&g_featT[(nbase + g) * R + rbi * 8 + tg2] =
                make_float2(acc[rbi][0], acc[rbi][1]);
            *(float2*)&g_featT[(nbase + g + 8) * R + rbi * 8 + tg2] =
                make_float2(acc[rbi][2], acc[rbi][3]);
        }
    }

    sps[sp_ch][sp_n] = sp;
    __syncthreads();
    if (tid < TN)
        g_sp[(size_t)b * HW + n0 + tid] = sps[0][tid] + sps[1][tid];
    for (int idx = tid; idx < C; idx += T1)
        g_poolpart[((size_t)(b * NSLOT) + tile) * C + idx] = spool[idx];
}

// ============================================================================
// Pass 2a: raw Gram partials from featT + pooled reduction for this CTA's
// channel quarter. CTA = (b, quarter q), 256 threads.
// ============================================================================
__global__ __launch_bounds__(256) void pass2a() {
    __shared__ __align__(16) float fcT[256][36];
    int b = blockIdx.x >> 2;
    int q = blockIdx.x & 3;
    int tid = threadIdx.x;

    const float* src = g_featT + ((size_t)b * HW + q * 256) * R;
    for (int it = 0; it < 32; it++) {
        int idx = tid + it * 256;
        fcT[idx >> 5][idx & 31] = src[idx];
    }

    // pooled for channels [q*128, q*128+128): 128 threads, 16 slots each
    if (tid < 128) {
        int c = q * 128 + tid;
        float s = 0.f;
#pragma unroll
        for (int k = 0; k < NSLOT; k++)
            s += g_poolpart[((size_t)b * NSLOT + k) * C + c];
        g_pool[(size_t)b * C + c] = s * (1.0f / HW);
    }
    __syncthreads();

    int my_r = tid >> 3;
    int s0 = (tid & 7) << 2;
    float g4[4] = {0.f, 0.f, 0.f, 0.f};
#pragma unroll 8
    for (int n = 0; n < 256; n++) {
        float fr = fcT[n][my_r];
        float4 fs = *(const float4*)&fcT[n][s0];
        g4[0] = fmaf(fr, fs.x, g4[0]);
        g4[1] = fmaf(fr, fs.y, g4[1]);
        g4[2] = fmaf(fr, fs.z, g4[2]);
        g4[3] = fmaf(fr, fs.w, g4[3]);
    }
    *(float4*)&g_covpart[((size_t)(b * 4 + q)) * (R * R) + my_r * R + s0] =
        make_float4(g4[0], g4[1], g4[2], g4[3]);
}

// ============================================================================
// Pass 2b: per-batch: g_pool -> ca1 + mu (batched loads); cov assembly;
// power iteration. Writes g_ca1 / g_v / g_c0.
// ============================================================================
__global__ __launch_bounds__(256) void pass2b(const float* __restrict__ w_fc1,
                                              const float* __restrict__ b_fc1,
                                              const float* __restrict__ w_eig,
                                              const float* __restrict__ v0) {
    __shared__ float s_pool[C];
    __shared__ float s_mu[R];
    __shared__ float s_cov[R * R];

    int b = blockIdx.x;
    int tid = threadIdx.x, lane = tid & 31, warp = tid >> 5;

    // 1. stage pooled (2 coalesced loads per thread)
    s_pool[tid] = g_pool[(size_t)b * C + tid];
    s_pool[tid + 256] = g_pool[(size_t)b * C + tid + 256];
    __syncthreads();

    // 2. ca1 = relu(pooled @ w_fc1^T + b_fc1); mu = w_eig @ pooled
#pragma unroll
    for (int k = 0; k < 4; k++) {
        int r = warp + k * 8;
        float s1 = 0.f, s2 = 0.f;
#pragma unroll
        for (int ci = 0; ci < 16; ci++) {
            int c = lane + ci * 32;
            float p = s_pool[c];
            s1 = fmaf(p, w_fc1[r * C + c], s1);
            s2 = fmaf(p, w_eig[r * C + c], s2);
        }
#pragma unroll
        for (int o = 16; o > 0; o >>= 1) {
            s1 += __shfl_xor_sync(0xffffffffu, s1, o);
            s2 += __shfl_xor_sync(0xffffffffu, s2, o);
        }
        if (lane == 0) {
            g_ca1[b * R + r] = fmaxf(s1 + b_fc1[r], 0.f);
            s_mu[r] = s2;
        }
    }
    __syncthreads();

    // 3. cov = (sum_q G_q - HW*mu*mu^T)/(HW-1) + 1e-5 I
#pragma unroll
    for (int i = 0; i < 4; i++) {
        int e = tid * 4 + i;
        if (e < R * R) {
            int r = e >> 5, s = e & 31;
            float gg = 0.f;
#pragma unroll
            for (int q = 0; q < 4; q++)
                gg += g_covpart[((size_t)(b * 4 + q)) * (R * R) + e];
            float v = (gg - (float)HW * s_mu[r] * s_mu[s]) * (1.0f / (HW - 1));
            if (r == s) v += 1e-5f;
            s_cov[e] = v;
        }
    }
    __syncthreads();

    // 4. power iteration (warp 0); write v and c0 = v.mu
    if (warp == 0) {
        float v = v0[b * R + lane];
        float nr = v * v;
#pragma unroll
        for (int o = 16; o > 0; o >>= 1) nr += __shfl_xor_sync(0xffffffffu, nr, o);
        v = v / sqrtf(nr);
#pragma unroll
        for (int it = 0; it < 5; it++) {
            float nv = 0.f;
#pragma unroll
            for (int s = 0; s < R; s++)
                nv = fmaf(s_cov[s * R + lane], __shfl_sync(0xffffffffu, v, s), nv);
            float nn = nv * nv;
#pragma unroll
            for (int o = 16; o > 0; o >>= 1) nn += __shfl_xor_sync(0xffffffffu, nn, o);
            v = nv / (sqrtf(nn) + 1e-10f);
        }
        g_v[b * R + lane] = v;
        float c0 = v * s_mu[lane];
#pragma unroll
        for (int o = 16; o > 0; o >>= 1) c0 += __shfl_xor_sync(0xffffffffu, c0, o);
        if (lane == 0) g_c0[b] = c0;
    }
}

// ============================================================================
// pass_post: merged attv + min/max + sigmoids + channel attention.
// Grid B, 1024 threads (one n per thread; threads < 512 also do one c).
// Replaces pass_ca / pass_att / pass_fin; no g_attraw round-trip.
// ============================================================================
__global__ __launch_bounds__(1024) void pass_post(const float* __restrict__ w_fc2,
                                                  const float* __restrict__ b_fc2,
                                                  const float* __restrict__ b_sp) {
    __shared__ float s_v[R], s_ca1[R];
    __shared__ float s_mn[32], s_mx[32];
    __shared__ float s_amin, s_denom;

    int b = blockIdx.x;
    int tid = threadIdx.x, lane = tid & 31, warp = tid >> 5;
    if (tid < R) {
        s_v[tid] = g_v[b * R + tid];
        s_ca1[tid] = g_ca1[b * R + tid];
    }
    __syncthreads();

    // attv = v . featT[n] - c0  (coalesced 128B row per thread)
    const float4* fp = (const float4*)&g_featT[((size_t)b * HW + tid) * R];
    float a = 0.f;
#pragma unroll
    for (int q = 0; q < 8; q++) {
        float4 f = fp[q];
        a = fmaf(s_v[q * 4 + 0], f.x, a);
        a = fmaf(s_v[q * 4 + 1], f.y, a);
        a = fmaf(s_v[q * 4 + 2], f.z, a);
        a = fmaf(s_v[q * 4 + 3], f.w, a);
    }
    float attv = a - g_c0[b];

    // block-wide min/max
    float mn = attv, mx = attv;
#pragma unroll
    for (int o = 16; o > 0; o >>= 1) {
        mn = fminf(mn, __shfl_xor_sync(0xffffffffu, mn, o));
        mx = fmaxf(mx, __shfl_xor_sync(0xffffffffu, mx, o));
    }
    if (lane == 0) { s_mn[warp] = mn; s_mx[warp] = mx; }
    __syncthreads();
    if (warp == 0) {
        float a0 = s_mn[lane], m0 = s_mx[lane];
#pragma unroll
        for (int o = 16; o > 0; o >>= 1) {
            a0 = fminf(a0, __shfl_xor_sync(0xffffffffu, a0, o));
            m0 = fmaxf(m0, __shfl_xor_sync(0xffffffffu, m0, o));
        }
        if (lane == 0) { s_amin = a0; s_denom = (m0 - a0) + 1e-10f; }
    }
    __syncthreads();

    float e = 1.f / (1.f + expf(-((attv - s_amin) / s_denom)));
    float sl = g_sp[(size_t)b * HW + tid] + b_sp[0];
    float sa = 1.f / (1.f + expf(-sl));
    g_att[(size_t)b * HW + tid] = e * sa;

    // channel attention (threads < 512, one c each)
    if (tid < C) {
        const float4* wrow = (const float4*)&w_fc2[tid * R];
        float aa = b_fc2[tid];
#pragma unroll
        for (int q = 0; q < 8; q++) {
            float4 w = wrow[q];
            aa = fmaf(s_ca1[q * 4 + 0], w.x, aa);
            aa = fmaf(s_ca1[q * 4 + 1], w.y, aa);
            aa = fmaf(s_ca1[q * 4 + 2], w.z, aa);
            aa = fmaf(s_ca1[q * 4 + 3], w.w, aa);
        }
        g_ca[(size_t)b * C + tid] = 1.f / (1.f + expf(-aa));
    }
}

// ============================================================================
// Pass 3: out = x * (1 + ca[b,c] * att[b,n])  (unchanged)
// ============================================================================
__global__ __launch_bounds__(256) void pass3(const float* __restrict__ x,
                                             float* __restrict__ out) {
    unsigned int base = blockIdx.x * 512u + threadIdx.x;
#pragma unroll
    for (int u = 0; u < 2; u++) {
        unsigned int i = base + u * 256u;      // float4 index
        int n4 = i & 255;                      // HW/4 = 256
        int c = (i >> 8) & (C - 1);
        int b = i >> 17;
        float ca = g_ca[b * C + c];
        float4 at = ((const float4*)g_att)[(size_t)b * (HW / 4) + n4];
        float4 xv = ((const float4*)x)[i];
        float4 o;
        o.x = fmaf(xv.x, ca * at.x, xv.x);
        o.y = fmaf(xv.y, ca * at.y, xv.y);
        o.z = fmaf(xv.z, ca * at.z, xv.z);
        o.w = fmaf(xv.w, ca * at.w, xv.w);
        ((float4*)out)[i] = o;
    }
}

extern "C" void kernel_launch(void* const* d_in, const int* in_sizes, int n_in,
                              void* d_out, int out_size) {
    const float* x     = (const float*)d_in[0];
    const float* w_fc1 = (const float*)d_in[1];
    const float* b_fc1 = (const float*)d_in[2];
    const float* w_fc2 = (const float*)d_in[3];
    const float* b_fc2 = (const float*)d_in[4];
    const float* w_eig = (const float*)d_in[5];
    /* d_in[6] = b_eig: cancels in feat_c and in mu -> unused */
    const float* w_sp  = (const float*)d_in[7];
    const float* b_sp  = (const float*)d_in[8];
    const float* v0    = (const float*)d_in[9];
    float* out = (float*)d_out;

    pass0<<<R * C / 256, 256>>>(w_eig);
    pass1<<<B * NTILE, T1>>>(x, w_sp);
    pass2a<<<B * 4, 256>>>();
    pass2b<<<B, 256>>>(w_fc1, b_fc1, w_eig, v0);
    pass_post<<<B, 1024>>>(w_fc2, b_fc2, b_sp);
    pass3<<<(B * C * HW / 4) / 512, 256>>>(x, out);
}